// round 10
// baseline (speedup 1.0000x reference)
#include <cuda_runtime.h>
#include <cstdint>

// EmbeddingWithDropout:
//   out[t, :] = weight[x[t], :] * ((u[x[t]] >= 0.1f) ? (1.0f/0.9f) : 0.0f)
// x: int32 [131072], weight: f32 [100000,128], u: f32 [100000], out: f32 [131072,128]
//
// Round-9: persistent software-pipelined kernel. Evidence R3-R8: kernel time
// pinned at 17.0±0.25us across MLP 3..16, halved instruction count, ±67MB DRAM
// traffic, predication => neither DRAM bw, nor L2, nor issue, nor MLP is the
// limiter. The invariant was the burst-wait-store-exit structure of 16K
// short-lived warps. This kernel keeps 4736 warps resident; each loops over
// chunks of 4 tokens with a 2-stage pipeline: while chunk c's row gathers are
// in flight, the indices+u for chunk c+stride are loaded, so the dependent
// idx->u chain head is off the critical path and load pressure is continuous
// rather than bursty.

#define TPW 4  // tokens per warp-chunk

__global__ void __launch_bounds__(256, 4)
embedding_dropout_kernel(const int* __restrict__ x,
                         const float4* __restrict__ weight,   // [vocab*32] float4
                         const float* __restrict__ u,         // [vocab]
                         float4* __restrict__ out,            // [n_tok*32] float4
                         int n_tok, int nchunks, int cstride)
{
    const int lane = threadIdx.x & 31;
    int c = blockIdx.x * (blockDim.x >> 5) + (threadIdx.x >> 5);

    int   rows[TPW];
    float uv[TPW];

    // Prologue: load indices + u for the first chunk.
    if (c < nchunks) {
        const int base = c * TPW;
        #pragma unroll
        for (int i = 0; i < TPW; i++) {
            const int tok = base + i;
            rows[i] = (tok < n_tok) ? __ldg(&x[tok]) : 0;
        }
        #pragma unroll
        for (int i = 0; i < TPW; i++)
            uv[i] = __ldg(&u[rows[i]]);
    }

    while (c < nchunks) {
        const int base = c * TPW;

        // Issue this chunk's row gathers (expensive wave).
        float4 v[TPW];
        #pragma unroll
        for (int i = 0; i < TPW; i++)
            v[i] = __ldg(&weight[(size_t)rows[i] * 32 + lane]);

        // Overlap: fetch NEXT chunk's indices + u while gathers are in flight.
        const int cn = c + cstride;
        int   rowsN[TPW];
        float uvN[TPW];
        if (cn < nchunks) {
            const int bn = cn * TPW;
            #pragma unroll
            for (int i = 0; i < TPW; i++) {
                const int tok = bn + i;
                rowsN[i] = (tok < n_tok) ? __ldg(&x[tok]) : 0;
            }
            #pragma unroll
            for (int i = 0; i < TPW; i++)
                uvN[i] = __ldg(&u[rowsN[i]]);
        }

        // Scale + store current chunk (first consumer of the gathers).
        #pragma unroll
        for (int i = 0; i < TPW; i++) {
            const float keep = (uv[i] >= 0.1f) ? (1.0f / 0.9f) : 0.0f;
            v[i].x *= keep;
            v[i].y *= keep;
            v[i].z *= keep;
            v[i].w *= keep;
            const int tok = base + i;
            if (tok < n_tok)
                out[(size_t)tok * 32 + lane] = v[i];
        }

        // Rotate pipeline.
        #pragma unroll
        for (int i = 0; i < TPW; i++) {
            rows[i] = rowsN[i];
            uv[i]   = uvN[i];
        }
        c = cn;
    }
}

extern "C" void kernel_launch(void* const* d_in, const int* in_sizes, int n_in,
                              void* d_out, int out_size)
{
    const int*    x      = (const int*)d_in[0];
    const float4* weight = (const float4*)d_in[1];
    const float*  u      = (const float*)d_in[2];
    float4*       out    = (float4*)d_out;

    const int n_tok = in_sizes[0];                 // 131072
    const int threads = 256;                       // 8 warps/block
    const int blocks  = 148 * 4;                   // persistent: 4 CTAs/SM
    const int warps_total = blocks * (threads / 32);   // 4736
    const int nchunks = (n_tok + TPW - 1) / TPW;       // 32768

    embedding_dropout_kernel<<<blocks, threads>>>(x, weight, u, out,
                                                  n_tok, nchunks, warps_total);
}

// round 11
// speedup vs baseline: 1.1065x; 1.1065x over previous
#include <cuda_runtime.h>
#include <cstdint>

// EmbeddingWithDropout:
//   out[t, :] = weight[x[t], :] * ((u[x[t]] >= 0.1f) ? (1.0f/0.9f) : 0.0f)
// x: int32 [131072], weight: f32 [100000,128], u: f32 [100000], out: f32 [131072,128]
//
// One warp handles 8 tokens; each lane owns one float4 of the 128-wide row
// (32 x 16 B = 512 B, coalesced gather + store).
//
// Round-10: steady-state (graph-replay) analysis across R3-R9 shows bench time
// tracks the STORE cache policy: __stcs 16.86us < evict_first 17.15 < plain
// 18.94 < wt 19.55. The 67MB output stream decides whether the 51MB table stays
// L2-resident between replays. So: revert to the best config (__stcs streaming
// stores, 2-wave batched gathers, grid 2048) and add the one untried traffic
// reducer: predicated gathers — ~10% of tokens are dropped (keep==0), their
// 512B row read is skipped entirely (warp-uniform branch, predicated-off LDG
// issues no transaction), cutting both LTS read and DRAM refill traffic.

#define TOK_PER_WARP 8

__global__ void __launch_bounds__(256, 4)
embedding_dropout_kernel(const int* __restrict__ x,
                         const float4* __restrict__ weight,   // [vocab*32] float4
                         const float* __restrict__ u,         // [vocab]
                         float4* __restrict__ out,            // [n_tok*32] float4
                         int n_tok)
{
    const int gtid = blockIdx.x * blockDim.x + threadIdx.x;
    const int warp = gtid >> 5;
    const int lane = threadIdx.x & 31;
    const int base = warp * TOK_PER_WARP;
    if (base >= n_tok) return;

    if (base + TOK_PER_WARP <= n_tok) {
        // ---- Wave 1: 8 independent index loads (uniform broadcast) ----
        int rows[TOK_PER_WARP];
        #pragma unroll
        for (int i = 0; i < TOK_PER_WARP; i++)
            rows[i] = __ldg(&x[base + i]);

        // ---- Wave 2: 8 u-loads (tiny, L2-resident) ----
        float uv[TOK_PER_WARP];
        #pragma unroll
        for (int i = 0; i < TOK_PER_WARP; i++)
            uv[i] = __ldg(&u[rows[i]]);

        // ---- Wave 3: predicated row gathers — dropped rows read NOTHING ----
        float4 v[TOK_PER_WARP];
        #pragma unroll
        for (int i = 0; i < TOK_PER_WARP; i++) {
            v[i] = make_float4(0.f, 0.f, 0.f, 0.f);
            if (uv[i] >= 0.1f)   // warp-uniform; predicated-off LDG = no traffic
                v[i] = __ldg(&weight[(size_t)rows[i] * 32 + lane]);
        }

        // ---- Scale + STREAMING store (output = L2 eviction victim) ----
        #pragma unroll
        for (int i = 0; i < TOK_PER_WARP; i++) {
            v[i].x *= (1.0f / 0.9f);
            v[i].y *= (1.0f / 0.9f);
            v[i].z *= (1.0f / 0.9f);
            v[i].w *= (1.0f / 0.9f);
            __stcs(&out[(size_t)(base + i) * 32 + lane], v[i]);
        }
    } else {
        // ---- Tail path ----
        for (int i = 0; base + i < n_tok; i++) {
            const int row = __ldg(&x[base + i]);
            const float uvt = __ldg(&u[row]);
            float4 v = make_float4(0.f, 0.f, 0.f, 0.f);
            if (uvt >= 0.1f)
                v = __ldg(&weight[(size_t)row * 32 + lane]);
            v.x *= (1.0f / 0.9f);
            v.y *= (1.0f / 0.9f);
            v.z *= (1.0f / 0.9f);
            v.w *= (1.0f / 0.9f);
            __stcs(&out[(size_t)(base + i) * 32 + lane], v);
        }
    }
}

extern "C" void kernel_launch(void* const* d_in, const int* in_sizes, int n_in,
                              void* d_out, int out_size)
{
    const int*    x      = (const int*)d_in[0];
    const float4* weight = (const float4*)d_in[1];
    const float*  u      = (const float*)d_in[2];
    float4*       out    = (float4*)d_out;

    const int n_tok = in_sizes[0];                            // 131072
    const int threads = 256;                                  // 8 warps/block
    const int tok_per_block = (threads / 32) * TOK_PER_WARP;  // 64
    const int blocks = (n_tok + tok_per_block - 1) / tok_per_block;

    embedding_dropout_kernel<<<blocks, threads>>>(x, weight, u, out, n_tok);
}